// round 4
// baseline (speedup 1.0000x reference)
#include <cuda_runtime.h>
#include <cstdint>

typedef unsigned long long u64;

#define BN      131072          // B*N
#define NPROP   16384
#define BIMG    8
#define M_ENT   32768           // N*(C-1)
#define CLU     8               // CTAs per image (cluster)
#define T       256             // threads per CTA
#define SLOTS   16              // register slots per thread (worst case 32768/2048)
#define STRIDE  (CLU * T)       // 2048
#define NEGF    (-1e9f)
#define HALF_NEG (-5e8f)
#define NMS_ITERS 640
#define DET     320
#define BBOX_CLIP_F 4.135166556742356f

// static device scratch (no allocation allowed)
__device__ float4 g_box  [BIMG * M_ENT];   // clipped boxes by ORIGINAL index (output)
__device__ float4 g_cnbox[BIMG * M_ENT];   // compacted offset boxes
__device__ u64    g_ckey [BIMG * M_ENT];   // compacted packed keys
__device__ int    g_cnt  [BIMG];

__device__ __forceinline__ u64 pack_key(float s, unsigned j)
{
    unsigned fb = __float_as_uint(s);
    fb = (fb & 0x80000000u) ? ~fb : (fb | 0x80000000u);   // sortable float
    return ((u64)fb << 32) | (u64)(0xFFFFFFFFu - j);
}

__device__ __forceinline__ float key_score(u64 k)
{
    unsigned fb = (unsigned)(k >> 32);
    unsigned orig = (fb & 0x80000000u) ? (fb ^ 0x80000000u) : ~fb;
    return __uint_as_float(orig);
}

__global__ void zero_kernel()
{
    if (threadIdx.x < BIMG) g_cnt[threadIdx.x] = 0;
}

// ---------------------------------------------------------------------------
// Prep: decode + softmax + clip + validity + warp-aggregated compaction
// ---------------------------------------------------------------------------
__global__ void prep_kernel(const float* __restrict__ logits,
                            const float* __restrict__ breg,
                            const float* __restrict__ props)
{
    int g = blockIdx.x * blockDim.x + threadIdx.x;
    if (g >= BN) return;
    int b = g >> 14;
    int n = g & (NPROP - 1);
    int lane = threadIdx.x & 31;

    float l0 = logits[g * 3 + 0];
    float l1 = logits[g * 3 + 1];
    float l2 = logits[g * 3 + 2];
    float mx = fmaxf(l0, fmaxf(l1, l2));
    float e0 = expf(l0 - mx), e1 = expf(l1 - mx), e2 = expf(l2 - mx);
    float sum = e0 + e1 + e2;
    float sc[2] = { e1 / sum, e2 / sum };

    float px1 = props[g * 4 + 0];
    float py1 = props[g * 4 + 1];
    float px2 = props[g * 4 + 2];
    float py2 = props[g * 4 + 3];
    float w  = px2 - px1;
    float h  = py2 - py1;
    float cx = px1 + 0.5f * w;
    float cy = py1 + 0.5f * h;

    const float fs = 1024.0f;

    float4 bx[2], nbx[2];
    bool   valid[2];
    #pragma unroll
    for (int c = 1; c <= 2; c++) {
        float r0 = breg[g * 12 + 4 * c + 0];
        float r1 = breg[g * 12 + 4 * c + 1];
        float r2 = breg[g * 12 + 4 * c + 2];
        float r3 = breg[g * 12 + 4 * c + 3];
        float dx = r0 / 10.0f;
        float dy = r1 / 10.0f;
        float dw = fminf(r2 / 5.0f, BBOX_CLIP_F);
        float dh = fminf(r3 / 5.0f, BBOX_CLIP_F);
        float pcx = dx * w + cx;
        float pcy = dy * h + cy;
        float pw = expf(dw) * w;
        float ph = expf(dh) * h;
        float x1 = pcx - 0.5f * pw;
        float y1 = pcy - 0.5f * ph;
        float x2 = pcx + 0.5f * pw;
        float y2 = pcy + 0.5f * ph;
        x1 = fminf(fmaxf(x1, 0.0f), fs);
        y1 = fminf(fmaxf(y1, 0.0f), fs);
        x2 = fminf(fmaxf(x2, 0.0f), fs);
        y2 = fminf(fmaxf(y2, 0.0f), fs);

        float s = sc[c - 1];
        valid[c - 1] = (s > 0.3f) && ((x2 - x1) >= 0.01f) && ((y2 - y1) >= 0.01f);
        float off = (float)c * (fs + 1.0f);   // 1025 / 2050 (exact)
        bx[c - 1]  = make_float4(x1, y1, x2, y2);
        nbx[c - 1] = make_float4(x1 + off, y1 + off, x2 + off, y2 + off);
    }

    // warp-aggregated compaction (warp never crosses an image: 16384 % 32 == 0)
    unsigned m1 = __ballot_sync(0xffffffffu, valid[0]);
    unsigned m2 = __ballot_sync(0xffffffffu, valid[1]);
    int basepos = 0;
    if (lane == 0) basepos = atomicAdd(&g_cnt[b], __popc(m1) + __popc(m2));
    basepos = __shfl_sync(0xffffffffu, basepos, 0);
    unsigned lt = (1u << lane) - 1u;

    int obase = b * M_ENT;
    if (valid[0]) {
        int pos = basepos + __popc(m1 & lt);
        unsigned m = 2u * n + 0u;
        g_cnbox[obase + pos] = nbx[0];
        g_ckey [obase + pos] = pack_key(sc[0], m);
        g_box  [obase + m]   = bx[0];
    }
    if (valid[1]) {
        int pos = basepos + __popc(m1) + __popc(m2 & lt);
        unsigned m = 2u * n + 1u;
        g_cnbox[obase + pos] = nbx[1];
        g_ckey [obase + pos] = pack_key(sc[1], m);
        g_box  [obase + m]   = bx[1];
    }
}

// ---------------------------------------------------------------------------
// cluster helpers
// ---------------------------------------------------------------------------
__device__ __forceinline__ uint32_t smem_u32(const void* p)
{
    uint32_t a;
    asm("{ .reg .u64 t; cvta.to.shared.u64 t, %1; cvt.u32.u64 %0, t; }"
        : "=r"(a) : "l"(p));
    return a;
}

__device__ __forceinline__ void st_cluster64(uint32_t laddr, uint32_t rank, u64 v)
{
    uint32_t r;
    asm volatile("mapa.shared::cluster.u32 %0, %1, %2;" : "=r"(r) : "r"(laddr), "r"(rank));
    asm volatile("st.shared::cluster.b64 [%0], %1;" :: "r"(r), "l"(v) : "memory");
}

__device__ __forceinline__ void arrive_release_cluster(uint32_t laddr, uint32_t rank)
{
    uint32_t r;
    asm volatile("mapa.shared::cluster.u32 %0, %1, %2;" : "=r"(r) : "r"(laddr), "r"(rank));
    asm volatile("mbarrier.arrive.release.cluster.shared::cluster.b64 _, [%0];"
                 :: "r"(r) : "memory");
}

__device__ __forceinline__ void wait_parity_acq_cluster(uint32_t a, uint32_t ph)
{
    asm volatile(
        "{\n\t"
        ".reg .pred P;\n\t"
        "W_%=:\n\t"
        "mbarrier.try_wait.parity.acquire.cluster.shared::cta.b64 P, [%0], %1, 0x989680;\n\t"
        "@P bra D_%=;\n\t"
        "bra W_%=;\n\t"
        "D_%=:\n\t"
        "}"
        :: "r"(a), "r"(ph) : "memory");
}

// ---------------------------------------------------------------------------
// NMS: cluster of 8x256; registers only; mbarrier DSMEM exchange per iter
// ---------------------------------------------------------------------------
__global__ void __launch_bounds__(T, 1) __cluster_dims__(CLU, 1, 1)
nms_kernel(float* __restrict__ out)
{
    __shared__ u64    xKeys[2][CLU];      // [parity][source rank]
    __shared__ float4 xBox [2][CLU];
    __shared__ u64    warpKey[2][T / 32];
    __shared__ u64    mbar[2];
    __shared__ unsigned recIdx[NMS_ITERS];
    __shared__ float    recScore[NMS_ITERS];
    __shared__ int      slots[NMS_ITERS];

    const int t = threadIdx.x;
    const int wrp = t >> 5;
    uint32_t rank;
    asm("mov.u32 %0, %%cluster_ctarank;" : "=r"(rank));
    const int b = blockIdx.x >> 3;
    const int base = b * M_ENT;

    const uint32_t keysA = smem_u32(&xKeys[0][0]);
    const uint32_t boxA  = smem_u32(&xBox[0][0]);
    const uint32_t mbarA = smem_u32(&mbar[0]);

    if (t == 0) {
        asm volatile("mbarrier.init.shared.b64 [%0], %1;" :: "r"(mbarA),     "r"(CLU) : "memory");
        asm volatile("mbarrier.init.shared.b64 [%0], %1;" :: "r"(mbarA + 8), "r"(CLU) : "memory");
    }
    __syncthreads();
    asm volatile("barrier.cluster.arrive.aligned;" ::: "memory");
    asm volatile("barrier.cluster.wait.aligned;"   ::: "memory");

    const int cnt = g_cnt[b];

    // owned entries (round-robin across cluster for load balance)
    u64    key[SLOTS];
    float4 nb [SLOTS];
    float  area[SLOTS];
    #pragma unroll
    for (int e = 0; e < SLOTS; e++) {
        int c = e * STRIDE + (int)rank * T + t;
        if (c < cnt) {
            key[e]  = g_ckey [base + c];
            nb[e]   = g_cnbox[base + c];
            area[e] = (nb[e].z - nb[e].x) * (nb[e].w - nb[e].y);
        } else {
            key[e]  = 0ull;
            nb[e]   = make_float4(0.f, 0.f, 0.f, 0.f);
            area[e] = 0.f;
        }
    }

    bool dirty = true;
    u64 lmax = 0ull;
    float4 wbox = nb[0];

    for (int it = 0; it < NMS_ITERS; ++it) {
        const int p  = it & 1;
        const uint32_t ph = (uint32_t)((it >> 1) & 1);

        // 1. cached local argmax (tracks winning box)
        if (dirty) {
            lmax = 0ull;
            #pragma unroll
            for (int e = 0; e < SLOTS; e++)
                if (key[e] > lmax) { lmax = key[e]; wbox = nb[e]; }
            dirty = false;
        }

        // 2. warp reduce via two redux.sync.max.u32
        unsigned hi = (unsigned)(lmax >> 32);
        unsigned lo = (unsigned)lmax;
        unsigned mhi = __reduce_max_sync(0xffffffffu, hi);
        unsigned mlo = __reduce_max_sync(0xffffffffu, (hi == mhi) ? lo : 0u);
        if ((t & 31) == 0) warpKey[p][wrp] = ((u64)mhi << 32) | mlo;
        __syncthreads();

        // 3. block max (all threads, broadcast smem reads; no 2nd barrier)
        u64 ck = warpKey[p][0];
        #pragma unroll
        for (int wi = 1; wi < T / 32; wi++) {
            u64 k2 = warpKey[p][wi];
            ck = (k2 > ck) ? k2 : ck;
        }

        // 4. single writer per CTA multicasts key+box, then arrives on peers
        if (lmax == ck && (ck != 0ull || t == 0)) {
            u64 v0 = ((u64)__float_as_uint(wbox.y) << 32) | (u64)__float_as_uint(wbox.x);
            u64 v1 = ((u64)__float_as_uint(wbox.w) << 32) | (u64)__float_as_uint(wbox.z);
            uint32_t kslot = keysA + (uint32_t)(p * CLU + rank) * 8u;
            uint32_t bslot = boxA  + (uint32_t)(p * CLU + rank) * 16u;
            #pragma unroll
            for (uint32_t r = 0; r < CLU; r++) {
                st_cluster64(kslot,      r, ck);
                st_cluster64(bslot,      r, v0);
                st_cluster64(bslot + 8u, r, v1);
            }
            #pragma unroll
            for (uint32_t r = 0; r < CLU; r++)
                arrive_release_cluster(mbarA + (uint32_t)p * 8u, r);
        }

        // 5. wait for all 8 ranks
        wait_parity_acq_cluster(mbarA + (uint32_t)p * 8u, ph);

        // 6. global winner (max + argmax over 8 rank keys)
        u64 wk = xKeys[p][0];
        int wr = 0;
        #pragma unroll
        for (int r = 1; r < CLU; r++) {
            u64 k2 = xKeys[p][r];
            if (k2 > wk) { wk = k2; wr = r; }
        }
        float4 sb = xBox[p][wr];
        float a1 = (sb.z - sb.x) * (sb.w - sb.y);
        unsigned wlo = (unsigned)wk;

        if (rank == 0 && t == 0) {
            recIdx[it]   = 0xFFFFFFFFu - wlo;
            recScore[it] = key_score(wk);
        }

        // 7. suppress live owned entries (registers only)
        #pragma unroll
        for (int e = 0; e < SLOTS; e++) {
            if (key[e] != 0ull) {
                float ltx = fmaxf(sb.x, nb[e].x);
                float lty = fmaxf(sb.y, nb[e].y);
                float rbx = fminf(sb.z, nb[e].z);
                float rby = fminf(sb.w, nb[e].w);
                float iw = fmaxf(rbx - ltx, 0.0f);
                float ih = fmaxf(rby - lty, 0.0f);
                float inter = iw * ih;
                float iou = inter / (a1 + area[e] - inter);
                if (iou > 0.3f || (unsigned)key[e] == wlo) { key[e] = 0ull; dirty = true; }
            }
        }
    }

    // ------------------- epilogue (rank-0 CTA of each image) ---------------
    __syncthreads();
    if (rank != 0) return;

    float* oBoxes  = out;                         // [8][320][4]
    float* oScores = out + BIMG * DET * 4;        // [8][320]
    float* oLabels = out + BIMG * DET * 5;        // [8][320]

    for (int q = t; q < DET * 4; q += T) oBoxes[b * DET * 4 + q] = 0.0f;
    for (int q = t; q < DET;     q += T) { oScores[b * DET + q] = 0.0f; oLabels[b * DET + q] = 0.0f; }

    if (t == 0) {
        int c0 = 0;
        for (int r = 0; r < NMS_ITERS; r++)
            if (recScore[r] > HALF_NEG && (recIdx[r] & 1u)) c0++;
        int p0 = 0, p1 = 0;
        for (int r = 0; r < NMS_ITERS; r++) {
            bool ok = recScore[r] > HALF_NEG;
            int slot = -1;
            if (ok) slot = (recIdx[r] & 1u) ? (p0++) : (c0 + p1++);
            slots[r] = slot;
        }
    }
    __syncthreads();

    for (int q = t; q < NMS_ITERS; q += T) {
        int slot = slots[q];
        if (slot >= 0 && slot < DET) {
            unsigned i = recIdx[q];
            float4 bx = g_box[base + i];
            float* dst = oBoxes + (b * DET + slot) * 4;
            dst[0] = bx.x; dst[1] = bx.y; dst[2] = bx.z; dst[3] = bx.w;
            oScores[b * DET + slot] = recScore[q];
            oLabels[b * DET + slot] = (float)((i & 1u) + 1u);
        }
    }
}

// ---------------------------------------------------------------------------
extern "C" void kernel_launch(void* const* d_in, const int* in_sizes, int n_in,
                              void* d_out, int out_size)
{
    (void)in_sizes; (void)n_in; (void)out_size;
    const float* logits = (const float*)d_in[0];
    const float* breg   = (const float*)d_in[1];
    const float* props  = (const float*)d_in[2];
    float* out = (float*)d_out;

    zero_kernel<<<1, 32>>>();
    prep_kernel<<<BN / 256, 256>>>(logits, breg, props);
    nms_kernel<<<BIMG * CLU, T>>>(out);
}

// round 5
// speedup vs baseline: 1.4427x; 1.4427x over previous
#include <cuda_runtime.h>
#include <cstdint>

typedef unsigned long long u64;

#define BN      131072          // B*N
#define NPROP   16384
#define BIMG    8
#define M_ENT   32768           // N*(C-1)
#define CLU     8               // CTAs per image (cluster)
#define T       256             // threads per CTA
#define STRIDE  (CLU * T)       // 2048
#define RSLOTS  8               // register-resident slots (boxes in regs)
#define TSLOTS  16              // total slots (worst case 32768/2048)
#define HALF_NEG (-5e8f)
#define NMS_ITERS 640
#define DET     320
#define BBOX_CLIP_F 4.135166556742356f

// static device scratch (no allocation allowed; zero-initialized at load)
__device__ float4 g_box  [BIMG * M_ENT];   // clipped boxes by ORIGINAL index
__device__ float4 g_cnbox[BIMG * M_ENT];   // compacted offset boxes
__device__ u64    g_ckey [BIMG * M_ENT];   // compacted packed keys
__device__ int    g_cnt  [BIMG];

__device__ __forceinline__ u64 pack_key(float s, unsigned j)
{
    unsigned fb = __float_as_uint(s);
    fb = (fb & 0x80000000u) ? ~fb : (fb | 0x80000000u);   // sortable float
    return ((u64)fb << 32) | (u64)(0xFFFFFFFFu - j);
}

__device__ __forceinline__ float key_score(u64 k)
{
    unsigned fb = (unsigned)(k >> 32);
    unsigned orig = (fb & 0x80000000u) ? (fb ^ 0x80000000u) : ~fb;
    return __uint_as_float(orig);
}

// ---------------------------------------------------------------------------
// Prep: decode + softmax + clip + validity + warp-aggregated compaction
// ---------------------------------------------------------------------------
__global__ void prep_kernel(const float* __restrict__ logits,
                            const float* __restrict__ breg,
                            const float* __restrict__ props)
{
    int g = blockIdx.x * blockDim.x + threadIdx.x;
    if (g >= BN) return;
    int b = g >> 14;
    int n = g & (NPROP - 1);
    int lane = threadIdx.x & 31;

    float l0 = logits[g * 3 + 0];
    float l1 = logits[g * 3 + 1];
    float l2 = logits[g * 3 + 2];
    float mx = fmaxf(l0, fmaxf(l1, l2));
    float e0 = expf(l0 - mx), e1 = expf(l1 - mx), e2 = expf(l2 - mx);
    float sum = e0 + e1 + e2;
    float sc[2] = { e1 / sum, e2 / sum };

    float px1 = props[g * 4 + 0];
    float py1 = props[g * 4 + 1];
    float px2 = props[g * 4 + 2];
    float py2 = props[g * 4 + 3];
    float w  = px2 - px1;
    float h  = py2 - py1;
    float cx = px1 + 0.5f * w;
    float cy = py1 + 0.5f * h;

    const float fs = 1024.0f;

    float4 bx[2], nbx[2];
    bool   valid[2];
    #pragma unroll
    for (int c = 1; c <= 2; c++) {
        float r0 = breg[g * 12 + 4 * c + 0];
        float r1 = breg[g * 12 + 4 * c + 1];
        float r2 = breg[g * 12 + 4 * c + 2];
        float r3 = breg[g * 12 + 4 * c + 3];
        float dx = r0 / 10.0f;
        float dy = r1 / 10.0f;
        float dw = fminf(r2 / 5.0f, BBOX_CLIP_F);
        float dh = fminf(r3 / 5.0f, BBOX_CLIP_F);
        float pcx = dx * w + cx;
        float pcy = dy * h + cy;
        float pw = expf(dw) * w;
        float ph = expf(dh) * h;
        float x1 = pcx - 0.5f * pw;
        float y1 = pcy - 0.5f * ph;
        float x2 = pcx + 0.5f * pw;
        float y2 = pcy + 0.5f * ph;
        x1 = fminf(fmaxf(x1, 0.0f), fs);
        y1 = fminf(fmaxf(y1, 0.0f), fs);
        x2 = fminf(fmaxf(x2, 0.0f), fs);
        y2 = fminf(fmaxf(y2, 0.0f), fs);

        float s = sc[c - 1];
        valid[c - 1] = (s > 0.3f) && ((x2 - x1) >= 0.01f) && ((y2 - y1) >= 0.01f);
        float off = (float)c * (fs + 1.0f);   // 1025 / 2050 (exact)
        bx[c - 1]  = make_float4(x1, y1, x2, y2);
        nbx[c - 1] = make_float4(x1 + off, y1 + off, x2 + off, y2 + off);
    }

    // warp-aggregated compaction (warps never cross an image: 16384 % 32 == 0)
    unsigned m1 = __ballot_sync(0xffffffffu, valid[0]);
    unsigned m2 = __ballot_sync(0xffffffffu, valid[1]);
    int basepos = 0;
    if (lane == 0) basepos = atomicAdd(&g_cnt[b], __popc(m1) + __popc(m2));
    basepos = __shfl_sync(0xffffffffu, basepos, 0);
    unsigned lt = (1u << lane) - 1u;

    int obase = b * M_ENT;
    if (valid[0]) {
        int pos = basepos + __popc(m1 & lt);
        unsigned m = 2u * n + 0u;
        g_cnbox[obase + pos] = nbx[0];
        g_ckey [obase + pos] = pack_key(sc[0], m);
        g_box  [obase + m]   = bx[0];
    }
    if (valid[1]) {
        int pos = basepos + __popc(m1) + __popc(m2 & lt);
        unsigned m = 2u * n + 1u;
        g_cnbox[obase + pos] = nbx[1];
        g_ckey [obase + pos] = pack_key(sc[1], m);
        g_box  [obase + m]   = bx[1];
    }
}

// ---------------------------------------------------------------------------
// cluster helpers
// ---------------------------------------------------------------------------
__device__ __forceinline__ uint32_t smem_u32(const void* p)
{
    uint32_t a;
    asm("{ .reg .u64 t; cvta.to.shared.u64 t, %1; cvt.u32.u64 %0, t; }"
        : "=r"(a) : "l"(p));
    return a;
}

__device__ __forceinline__ void fanout3(uint32_t laddr, uint32_t rank,
                                        u64 a, u64 b, u64 c)
{
    uint32_t r;
    asm volatile("mapa.shared::cluster.u32 %0, %1, %2;" : "=r"(r) : "r"(laddr), "r"(rank));
    asm volatile("st.shared::cluster.b64 [%0], %1;"      :: "r"(r),       "l"(a) : "memory");
    asm volatile("st.shared::cluster.b64 [%0+8], %1;"    :: "r"(r),       "l"(b) : "memory");
    asm volatile("st.shared::cluster.b64 [%0+16], %1;"   :: "r"(r),       "l"(c) : "memory");
}

// ---------------------------------------------------------------------------
// NMS: cluster 8x256, registers only, one cluster barrier per iteration
// ---------------------------------------------------------------------------
__global__ void __launch_bounds__(T, 1) __cluster_dims__(CLU, 1, 1)
nms_kernel(float* __restrict__ out)
{
    __shared__ u64 xch[2][CLU][3];          // [parity][src rank][key,v0,v1]
    __shared__ u64 warpKey[2][T / 32];
    __shared__ u64 xLocal[2];               // winner thread's box (v0,v1)
    __shared__ unsigned recIdx[NMS_ITERS];
    __shared__ float    recScore[NMS_ITERS];
    __shared__ int      slots[NMS_ITERS];

    const int t = threadIdx.x;
    const int wrp = t >> 5;
    uint32_t rank;
    asm("mov.u32 %0, %%cluster_ctarank;" : "=r"(rank));
    const int b = blockIdx.x >> 3;
    const int base = b * M_ENT;

    const uint32_t xchA = smem_u32(&xch[0][0][0]);

    const int cnt = g_cnt[b];

    // owned entries: slots 0..7 register-resident (boxes+areas), 8..15 keys only
    u64    key[TSLOTS];
    float4 nb [RSLOTS];
    float  area[RSLOTS];
    #pragma unroll
    for (int e = 0; e < RSLOTS; e++) {
        int c = e * STRIDE + (int)rank * T + t;
        if (c < cnt) {
            key[e]  = g_ckey [base + c];
            nb[e]   = g_cnbox[base + c];
            area[e] = (nb[e].z - nb[e].x) * (nb[e].w - nb[e].y);
        } else {
            key[e]  = 0ull;
            nb[e]   = make_float4(0.f, 0.f, 0.f, 0.f);
            area[e] = 0.f;
        }
    }
    const bool overflow = cnt > RSLOTS * STRIDE;    // uniform; false for this data
    #pragma unroll
    for (int e = RSLOTS; e < TSLOTS; e++) {
        int c = e * STRIDE + (int)rank * T + t;
        key[e] = (overflow && c < cnt) ? g_ckey[base + c] : 0ull;
    }

    bool dirty = true;
    u64 lmax = 0ull;
    float4 wbox = nb[0];

    for (int it = 0; it < NMS_ITERS; ++it) {
        const int p = it & 1;

        // 1. cached local argmax (tracks winning box)
        if (dirty) {
            lmax = 0ull;
            int we = -1;
            #pragma unroll
            for (int e = 0; e < RSLOTS; e++)
                if (key[e] > lmax) { lmax = key[e]; we = e; }
            if (we >= 0) wbox = nb[we];
            if (overflow) {
                int wo = -1;
                #pragma unroll
                for (int e = RSLOTS; e < TSLOTS; e++)
                    if (key[e] > lmax) { lmax = key[e]; wo = e; }
                if (wo >= 0) wbox = g_cnbox[base + wo * STRIDE + (int)rank * T + t];
            }
            dirty = false;
        }

        // 2. warp reduce via two redux.sync
        unsigned hi = (unsigned)(lmax >> 32);
        unsigned lo = (unsigned)lmax;
        unsigned mhi = __reduce_max_sync(0xffffffffu, hi);
        unsigned mlo = __reduce_max_sync(0xffffffffu, (hi == mhi) ? lo : 0u);
        if ((t & 31) == 0) warpKey[p][wrp] = ((u64)mhi << 32) | mlo;
        __syncthreads();

        // 3. block max: all threads scan 8 warp partials
        u64 ck = warpKey[p][0];
        #pragma unroll
        for (int wi = 1; wi < T / 32; wi++) {
            u64 k2 = warpKey[p][wi];
            ck = (k2 > ck) ? k2 : ck;
        }

        // 4. winner thread publishes its box locally
        if ((lmax == ck && ck != 0ull) || (ck == 0ull && t == 0)) {
            xLocal[0] = ((u64)__float_as_uint(wbox.y) << 32) | (u64)__float_as_uint(wbox.x);
            xLocal[1] = ((u64)__float_as_uint(wbox.w) << 32) | (u64)__float_as_uint(wbox.z);
        }
        __syncthreads();

        // 5. parallel fan-out: thread t<8 pushes key+box to rank t
        if (t < CLU) {
            u64 v0 = xLocal[0];
            u64 v1 = xLocal[1];
            fanout3(xchA + (uint32_t)(p * CLU + (int)rank) * 24u, (uint32_t)t, ck, v0, v1);
        }

        // 6. cluster barrier (arrive=release, wait=acquire)
        asm volatile("barrier.cluster.arrive.aligned;" ::: "memory");
        asm volatile("barrier.cluster.wait.aligned;"   ::: "memory");

        // 7. global winner over 8 rank keys
        u64 wk = xch[p][0][0];
        int wr = 0;
        #pragma unroll
        for (int r = 1; r < CLU; r++) {
            u64 k2 = xch[p][r][0];
            if (k2 > wk) { wk = k2; wr = r; }
        }
        u64 b0 = xch[p][wr][1];
        u64 b1 = xch[p][wr][2];
        float sx = __uint_as_float((unsigned)(b0 & 0xFFFFFFFFu));
        float sy = __uint_as_float((unsigned)(b0 >> 32));
        float sz = __uint_as_float((unsigned)(b1 & 0xFFFFFFFFu));
        float sw = __uint_as_float((unsigned)(b1 >> 32));
        float a1 = (sz - sx) * (sw - sy);
        unsigned wlo = (unsigned)wk;

        if (rank == 0 && t == 0) {
            recIdx[it]   = 0xFFFFFFFFu - wlo;
            recScore[it] = key_score(wk);     // NaN when wk==0 -> treated as not-ok
        }

        // 8. suppress live owned entries
        #pragma unroll
        for (int e = 0; e < RSLOTS; e++) {
            if (key[e] != 0ull) {
                float ltx = fmaxf(sx, nb[e].x);
                float lty = fmaxf(sy, nb[e].y);
                float rbx = fminf(sz, nb[e].z);
                float rby = fminf(sw, nb[e].w);
                float iw = fmaxf(rbx - ltx, 0.0f);
                float ih = fmaxf(rby - lty, 0.0f);
                float inter = iw * ih;
                float iou = inter / (a1 + area[e] - inter);
                if (iou > 0.3f || (unsigned)key[e] == wlo) { key[e] = 0ull; dirty = true; }
            }
        }
        if (overflow) {
            #pragma unroll
            for (int e = RSLOTS; e < TSLOTS; e++) {
                if (key[e] != 0ull) {
                    float4 c4 = g_cnbox[base + e * STRIDE + (int)rank * T + t];
                    float a2 = (c4.z - c4.x) * (c4.w - c4.y);
                    float ltx = fmaxf(sx, c4.x);
                    float lty = fmaxf(sy, c4.y);
                    float rbx = fminf(sz, c4.z);
                    float rby = fminf(sw, c4.w);
                    float iw = fmaxf(rbx - ltx, 0.0f);
                    float ih = fmaxf(rby - lty, 0.0f);
                    float inter = iw * ih;
                    float iou = inter / (a1 + a2 - inter);
                    if (iou > 0.3f || (unsigned)key[e] == wlo) { key[e] = 0ull; dirty = true; }
                }
            }
        }
    }

    // ------------------- epilogue (rank-0 CTA of each image) ---------------
    __syncthreads();
    if (rank != 0) return;

    float* oBoxes  = out;                         // [8][320][4]
    float* oScores = out + BIMG * DET * 4;        // [8][320]
    float* oLabels = out + BIMG * DET * 5;        // [8][320]

    for (int q = t; q < DET * 4; q += T) oBoxes[b * DET * 4 + q] = 0.0f;
    for (int q = t; q < DET;     q += T) { oScores[b * DET + q] = 0.0f; oLabels[b * DET + q] = 0.0f; }

    if (t == 0) {
        int c0 = 0;
        for (int r = 0; r < NMS_ITERS; r++)
            if (recScore[r] > HALF_NEG && (recIdx[r] & 1u)) c0++;
        int p0 = 0, p1 = 0;
        for (int r = 0; r < NMS_ITERS; r++) {
            bool ok = recScore[r] > HALF_NEG;
            int slot = -1;
            if (ok) slot = (recIdx[r] & 1u) ? (p0++) : (c0 + p1++);
            slots[r] = slot;
        }
    }
    __syncthreads();

    for (int q = t; q < NMS_ITERS; q += T) {
        int slot = slots[q];
        if (slot >= 0 && slot < DET) {
            unsigned i = recIdx[q];
            float4 bx = g_box[base + i];
            float* dst = oBoxes + (b * DET + slot) * 4;
            dst[0] = bx.x; dst[1] = bx.y; dst[2] = bx.z; dst[3] = bx.w;
            oScores[b * DET + slot] = recScore[q];
            oLabels[b * DET + slot] = (float)((i & 1u) + 1u);
        }
    }

    // self-clean the counter for the next (graph-replayed) launch
    if (t == 0) g_cnt[b] = 0;
}

// ---------------------------------------------------------------------------
extern "C" void kernel_launch(void* const* d_in, const int* in_sizes, int n_in,
                              void* d_out, int out_size)
{
    (void)in_sizes; (void)n_in; (void)out_size;
    const float* logits = (const float*)d_in[0];
    const float* breg   = (const float*)d_in[1];
    const float* props  = (const float*)d_in[2];
    float* out = (float*)d_out;

    prep_kernel<<<BN / 256, 256>>>(logits, breg, props);
    nms_kernel<<<BIMG * CLU, T>>>(out);
}

// round 6
// speedup vs baseline: 1.4743x; 1.0219x over previous
#include <cuda_runtime.h>
#include <cstdint>

typedef unsigned long long u64;

#define BN      131072          // B*N
#define NPROP   16384
#define BIMG    8
#define M_ENT   32768           // N*(C-1)
#define CLU     8               // CTAs per image (cluster)
#define T       256             // threads per CTA
#define STRIDE  (CLU * T)       // 2048
#define RSLOTS  8               // register-resident slots (boxes in regs)
#define TSLOTS  16              // total slots (worst case 32768/2048)
#define HALF_NEG (-5e8f)
#define NMS_ITERS 640
#define DET     320
#define BBOX_CLIP_F 4.135166556742356f

// static device scratch (no allocation allowed; zero-initialized at load)
__device__ float4 g_box  [BIMG * M_ENT];   // clipped boxes by ORIGINAL index
__device__ float4 g_cnbox[BIMG * M_ENT];   // compacted offset boxes
__device__ u64    g_ckey [BIMG * M_ENT];   // compacted packed keys
__device__ int    g_cnt  [BIMG];

__device__ __forceinline__ u64 pack_key(float s, unsigned j)
{
    unsigned fb = __float_as_uint(s);
    fb = (fb & 0x80000000u) ? ~fb : (fb | 0x80000000u);   // sortable float
    return ((u64)fb << 32) | (u64)(0xFFFFFFFFu - j);
}

__device__ __forceinline__ float key_score(u64 k)
{
    unsigned fb = (unsigned)(k >> 32);
    unsigned orig = (fb & 0x80000000u) ? (fb ^ 0x80000000u) : ~fb;
    return __uint_as_float(orig);
}

// ---------------------------------------------------------------------------
// Prep: decode + softmax + clip + validity + warp-aggregated compaction
// ---------------------------------------------------------------------------
__global__ void prep_kernel(const float* __restrict__ logits,
                            const float* __restrict__ breg,
                            const float* __restrict__ props)
{
    int g = blockIdx.x * blockDim.x + threadIdx.x;
    if (g >= BN) return;
    int b = g >> 14;
    int n = g & (NPROP - 1);
    int lane = threadIdx.x & 31;

    float l0 = logits[g * 3 + 0];
    float l1 = logits[g * 3 + 1];
    float l2 = logits[g * 3 + 2];
    float mx = fmaxf(l0, fmaxf(l1, l2));
    float e0 = expf(l0 - mx), e1 = expf(l1 - mx), e2 = expf(l2 - mx);
    float sum = e0 + e1 + e2;
    float sc[2] = { e1 / sum, e2 / sum };

    float px1 = props[g * 4 + 0];
    float py1 = props[g * 4 + 1];
    float px2 = props[g * 4 + 2];
    float py2 = props[g * 4 + 3];
    float w  = px2 - px1;
    float h  = py2 - py1;
    float cx = px1 + 0.5f * w;
    float cy = py1 + 0.5f * h;

    const float fs = 1024.0f;

    float4 bx[2], nbx[2];
    bool   valid[2];
    #pragma unroll
    for (int c = 1; c <= 2; c++) {
        float r0 = breg[g * 12 + 4 * c + 0];
        float r1 = breg[g * 12 + 4 * c + 1];
        float r2 = breg[g * 12 + 4 * c + 2];
        float r3 = breg[g * 12 + 4 * c + 3];
        float dx = r0 / 10.0f;
        float dy = r1 / 10.0f;
        float dw = fminf(r2 / 5.0f, BBOX_CLIP_F);
        float dh = fminf(r3 / 5.0f, BBOX_CLIP_F);
        float pcx = dx * w + cx;
        float pcy = dy * h + cy;
        float pw = expf(dw) * w;
        float ph = expf(dh) * h;
        float x1 = pcx - 0.5f * pw;
        float y1 = pcy - 0.5f * ph;
        float x2 = pcx + 0.5f * pw;
        float y2 = pcy + 0.5f * ph;
        x1 = fminf(fmaxf(x1, 0.0f), fs);
        y1 = fminf(fmaxf(y1, 0.0f), fs);
        x2 = fminf(fmaxf(x2, 0.0f), fs);
        y2 = fminf(fmaxf(y2, 0.0f), fs);

        float s = sc[c - 1];
        valid[c - 1] = (s > 0.3f) && ((x2 - x1) >= 0.01f) && ((y2 - y1) >= 0.01f);
        float off = (float)c * (fs + 1.0f);   // 1025 / 2050 (exact)
        bx[c - 1]  = make_float4(x1, y1, x2, y2);
        nbx[c - 1] = make_float4(x1 + off, y1 + off, x2 + off, y2 + off);
    }

    // warp-aggregated compaction (warps never cross an image: 16384 % 32 == 0)
    unsigned m1 = __ballot_sync(0xffffffffu, valid[0]);
    unsigned m2 = __ballot_sync(0xffffffffu, valid[1]);
    int basepos = 0;
    if (lane == 0) basepos = atomicAdd(&g_cnt[b], __popc(m1) + __popc(m2));
    basepos = __shfl_sync(0xffffffffu, basepos, 0);
    unsigned lt = (1u << lane) - 1u;

    int obase = b * M_ENT;
    if (valid[0]) {
        int pos = basepos + __popc(m1 & lt);
        unsigned m = 2u * n + 0u;
        g_cnbox[obase + pos] = nbx[0];
        g_ckey [obase + pos] = pack_key(sc[0], m);
        g_box  [obase + m]   = bx[0];
    }
    if (valid[1]) {
        int pos = basepos + __popc(m1) + __popc(m2 & lt);
        unsigned m = 2u * n + 1u;
        g_cnbox[obase + pos] = nbx[1];
        g_ckey [obase + pos] = pack_key(sc[1], m);
        g_box  [obase + m]   = bx[1];
    }
}

// ---------------------------------------------------------------------------
// cluster helpers
// ---------------------------------------------------------------------------
__device__ __forceinline__ uint32_t smem_u32(const void* p)
{
    uint32_t a;
    asm("{ .reg .u64 t; cvta.to.shared.u64 t, %1; cvt.u32.u64 %0, t; }"
        : "=r"(a) : "l"(p));
    return a;
}

__device__ __forceinline__ void fanout3(uint32_t laddr, uint32_t rank,
                                        u64 a, u64 b, u64 c)
{
    uint32_t r;
    asm volatile("mapa.shared::cluster.u32 %0, %1, %2;" : "=r"(r) : "r"(laddr), "r"(rank));
    asm volatile("st.shared::cluster.b64 [%0], %1;"      :: "r"(r),       "l"(a) : "memory");
    asm volatile("st.shared::cluster.b64 [%0+8], %1;"    :: "r"(r),       "l"(b) : "memory");
    asm volatile("st.shared::cluster.b64 [%0+16], %1;"   :: "r"(r),       "l"(c) : "memory");
}

// ---------------------------------------------------------------------------
// NMS: cluster 8x256, registers only, one cluster barrier per iteration,
// EXACT early exit when the candidate pool is exhausted.
// ---------------------------------------------------------------------------
__global__ void __launch_bounds__(T, 1) __cluster_dims__(CLU, 1, 1)
nms_kernel(float* __restrict__ out)
{
    __shared__ u64 xch[2][CLU][3];          // [parity][src rank][key,v0,v1]
    __shared__ u64 warpKey[2][T / 32];
    __shared__ u64 xLocal[2];               // winner thread's box (v0,v1)
    __shared__ unsigned recIdx[NMS_ITERS];
    __shared__ float    recScore[NMS_ITERS];
    __shared__ int      slots[NMS_ITERS];

    const int t = threadIdx.x;
    const int wrp = t >> 5;
    uint32_t rank;
    asm("mov.u32 %0, %%cluster_ctarank;" : "=r"(rank));
    const int b = blockIdx.x >> 3;
    const int base = b * M_ENT;

    const uint32_t xchA = smem_u32(&xch[0][0][0]);

    const int cnt = g_cnt[b];

    // owned entries: slots 0..7 register-resident (boxes+areas), 8..15 keys only
    u64    key[TSLOTS];
    float4 nb [RSLOTS];
    float  area[RSLOTS];
    #pragma unroll
    for (int e = 0; e < RSLOTS; e++) {
        int c = e * STRIDE + (int)rank * T + t;
        if (c < cnt) {
            key[e]  = g_ckey [base + c];
            nb[e]   = g_cnbox[base + c];
            area[e] = (nb[e].z - nb[e].x) * (nb[e].w - nb[e].y);
        } else {
            key[e]  = 0ull;
            nb[e]   = make_float4(0.f, 0.f, 0.f, 0.f);
            area[e] = 0.f;
        }
    }
    const bool overflow = cnt > RSLOTS * STRIDE;    // uniform; false for this data
    #pragma unroll
    for (int e = RSLOTS; e < TSLOTS; e++) {
        int c = e * STRIDE + (int)rank * T + t;
        key[e] = (overflow && c < cnt) ? g_ckey[base + c] : 0ull;
    }

    bool dirty = true;
    u64 lmax = 0ull;
    float4 wbox = nb[0];
    int nRec = NMS_ITERS;

    for (int it = 0; it < NMS_ITERS; ++it) {
        const int p = it & 1;

        // 1. cached local argmax (tracks winning box)
        if (dirty) {
            lmax = 0ull;
            int we = -1;
            #pragma unroll
            for (int e = 0; e < RSLOTS; e++)
                if (key[e] > lmax) { lmax = key[e]; we = e; }
            if (we >= 0) wbox = nb[we];
            if (overflow) {
                int wo = -1;
                #pragma unroll
                for (int e = RSLOTS; e < TSLOTS; e++)
                    if (key[e] > lmax) { lmax = key[e]; wo = e; }
                if (wo >= 0) wbox = g_cnbox[base + wo * STRIDE + (int)rank * T + t];
            }
            dirty = false;
        }

        // 2. warp reduce via two redux.sync
        unsigned hi = (unsigned)(lmax >> 32);
        unsigned lo = (unsigned)lmax;
        unsigned mhi = __reduce_max_sync(0xffffffffu, hi);
        unsigned mlo = __reduce_max_sync(0xffffffffu, (hi == mhi) ? lo : 0u);
        if ((t & 31) == 0) warpKey[p][wrp] = ((u64)mhi << 32) | mlo;
        __syncthreads();

        // 3. block max: all threads scan 8 warp partials
        u64 ck = warpKey[p][0];
        #pragma unroll
        for (int wi = 1; wi < T / 32; wi++) {
            u64 k2 = warpKey[p][wi];
            ck = (k2 > ck) ? k2 : ck;
        }

        // 4. winner thread publishes its box locally
        if ((lmax == ck && ck != 0ull) || (ck == 0ull && t == 0)) {
            xLocal[0] = ((u64)__float_as_uint(wbox.y) << 32) | (u64)__float_as_uint(wbox.x);
            xLocal[1] = ((u64)__float_as_uint(wbox.w) << 32) | (u64)__float_as_uint(wbox.z);
        }
        __syncthreads();

        // 5. parallel fan-out: thread t<8 pushes key+box to rank t
        if (t < CLU) {
            u64 v0 = xLocal[0];
            u64 v1 = xLocal[1];
            fanout3(xchA + (uint32_t)(p * CLU + (int)rank) * 24u, (uint32_t)t, ck, v0, v1);
        }

        // 6. cluster barrier (arrive=release, wait=acquire)
        asm volatile("barrier.cluster.arrive.aligned;" ::: "memory");
        asm volatile("barrier.cluster.wait.aligned;"   ::: "memory");

        // 7. global winner over 8 rank keys
        u64 wk = xch[p][0][0];
        int wr = 0;
        #pragma unroll
        for (int r = 1; r < CLU; r++) {
            u64 k2 = xch[p][r][0];
            if (k2 > wk) { wk = k2; wr = r; }
        }

        // EXACT early exit: no live entries anywhere -> every remaining
        // iteration of the reference is a no-op (ok=false, contributes zeros).
        if (wk == 0ull) { nRec = it; break; }

        u64 b0 = xch[p][wr][1];
        u64 b1 = xch[p][wr][2];
        float sx = __uint_as_float((unsigned)(b0 & 0xFFFFFFFFu));
        float sy = __uint_as_float((unsigned)(b0 >> 32));
        float sz = __uint_as_float((unsigned)(b1 & 0xFFFFFFFFu));
        float sw = __uint_as_float((unsigned)(b1 >> 32));
        float a1 = (sz - sx) * (sw - sy);
        unsigned wlo = (unsigned)wk;

        if (rank == 0 && t == 0) {
            recIdx[it]   = 0xFFFFFFFFu - wlo;
            recScore[it] = key_score(wk);
        }

        // 8. suppress live owned entries
        #pragma unroll
        for (int e = 0; e < RSLOTS; e++) {
            if (key[e] != 0ull) {
                float ltx = fmaxf(sx, nb[e].x);
                float lty = fmaxf(sy, nb[e].y);
                float rbx = fminf(sz, nb[e].z);
                float rby = fminf(sw, nb[e].w);
                float iw = fmaxf(rbx - ltx, 0.0f);
                float ih = fmaxf(rby - lty, 0.0f);
                float inter = iw * ih;
                float iou = inter / (a1 + area[e] - inter);
                if (iou > 0.3f || (unsigned)key[e] == wlo) { key[e] = 0ull; dirty = true; }
            }
        }
        if (overflow) {
            #pragma unroll
            for (int e = RSLOTS; e < TSLOTS; e++) {
                if (key[e] != 0ull) {
                    float4 c4 = g_cnbox[base + e * STRIDE + (int)rank * T + t];
                    float a2 = (c4.z - c4.x) * (c4.w - c4.y);
                    float ltx = fmaxf(sx, c4.x);
                    float lty = fmaxf(sy, c4.y);
                    float rbx = fminf(sz, c4.z);
                    float rby = fminf(sw, c4.w);
                    float iw = fmaxf(rbx - ltx, 0.0f);
                    float ih = fmaxf(rby - lty, 0.0f);
                    float inter = iw * ih;
                    float iou = inter / (a1 + a2 - inter);
                    if (iou > 0.3f || (unsigned)key[e] == wlo) { key[e] = 0ull; dirty = true; }
                }
            }
        }
    }

    // ------------------- epilogue (rank-0 CTA of each image) ---------------
    __syncthreads();
    if (rank != 0) return;

    float* oBoxes  = out;                         // [8][320][4]
    float* oScores = out + BIMG * DET * 4;        // [8][320]
    float* oLabels = out + BIMG * DET * 5;        // [8][320]

    for (int q = t; q < DET * 4; q += T) oBoxes[b * DET * 4 + q] = 0.0f;
    for (int q = t; q < DET;     q += T) { oScores[b * DET + q] = 0.0f; oLabels[b * DET + q] = 0.0f; }

    if (t == 0) {
        int c0 = 0;
        for (int r = 0; r < nRec; r++)
            if (recScore[r] > HALF_NEG && (recIdx[r] & 1u)) c0++;
        int p0 = 0, p1 = 0;
        for (int r = 0; r < nRec; r++) {
            bool ok = recScore[r] > HALF_NEG;
            int slot = -1;
            if (ok) slot = (recIdx[r] & 1u) ? (p0++) : (c0 + p1++);
            slots[r] = slot;
        }
    }
    __syncthreads();

    for (int q = t; q < nRec; q += T) {
        int slot = slots[q];
        if (slot >= 0 && slot < DET) {
            unsigned i = recIdx[q];
            float4 bx = g_box[base + i];
            float* dst = oBoxes + (b * DET + slot) * 4;
            dst[0] = bx.x; dst[1] = bx.y; dst[2] = bx.z; dst[3] = bx.w;
            oScores[b * DET + slot] = recScore[q];
            oLabels[b * DET + slot] = (float)((i & 1u) + 1u);
        }
    }

    // self-clean the counter for the next (graph-replayed) launch
    if (t == 0) g_cnt[b] = 0;
}

// ---------------------------------------------------------------------------
extern "C" void kernel_launch(void* const* d_in, const int* in_sizes, int n_in,
                              void* d_out, int out_size)
{
    (void)in_sizes; (void)n_in; (void)out_size;
    const float* logits = (const float*)d_in[0];
    const float* breg   = (const float*)d_in[1];
    const float* props  = (const float*)d_in[2];
    float* out = (float*)d_out;

    prep_kernel<<<BN / 256, 256>>>(logits, breg, props);
    nms_kernel<<<BIMG * CLU, T>>>(out);
}

// round 7
// speedup vs baseline: 1.7376x; 1.1786x over previous
#include <cuda_runtime.h>
#include <cstdint>

typedef unsigned long long u64;

#define BN      131072          // B*N
#define NPROP   16384
#define BIMG    8
#define M_ENT   32768           // N*(C-1)
#define CLU     8               // CTAs per image (cluster)
#define T       256             // threads per CTA
#define STRIDE  (CLU * T)       // 2048
#define RSLOTS  8               // register-resident slots (boxes in regs)
#define TSLOTS  16              // total slots (worst case 32768/2048)
#define CAND    8               // candidates exchanged per CTA per round
#define MC      (CLU * CAND)    // 64 merged candidates
#define HALF_NEG (-5e8f)
#define NMS_ITERS 640
#define DET     320
#define BBOX_CLIP_F 4.135166556742356f

// static device scratch (no allocation allowed; zero-initialized at load)
__device__ float4 g_box  [BIMG * M_ENT];   // clipped boxes by ORIGINAL index
__device__ float4 g_cnbox[BIMG * M_ENT];   // compacted offset boxes
__device__ u64    g_ckey [BIMG * M_ENT];   // compacted packed keys
__device__ int    g_cnt  [BIMG];

__device__ __forceinline__ u64 pack_key(float s, unsigned j)
{
    unsigned fb = __float_as_uint(s);
    fb = (fb & 0x80000000u) ? ~fb : (fb | 0x80000000u);   // sortable float
    return ((u64)fb << 32) | (u64)(0xFFFFFFFFu - j);
}

__device__ __forceinline__ float key_score(u64 k)
{
    unsigned fb = (unsigned)(k >> 32);
    unsigned orig = (fb & 0x80000000u) ? (fb ^ 0x80000000u) : ~fb;
    return __uint_as_float(orig);
}

// ---------------------------------------------------------------------------
// Prep: decode + softmax + clip + validity + warp-aggregated compaction
// ---------------------------------------------------------------------------
__global__ void prep_kernel(const float* __restrict__ logits,
                            const float* __restrict__ breg,
                            const float* __restrict__ props)
{
    int g = blockIdx.x * blockDim.x + threadIdx.x;
    if (g >= BN) return;
    int b = g >> 14;
    int n = g & (NPROP - 1);
    int lane = threadIdx.x & 31;

    float l0 = logits[g * 3 + 0];
    float l1 = logits[g * 3 + 1];
    float l2 = logits[g * 3 + 2];
    float mx = fmaxf(l0, fmaxf(l1, l2));
    float e0 = expf(l0 - mx), e1 = expf(l1 - mx), e2 = expf(l2 - mx);
    float sum = e0 + e1 + e2;
    float sc[2] = { e1 / sum, e2 / sum };

    float px1 = props[g * 4 + 0];
    float py1 = props[g * 4 + 1];
    float px2 = props[g * 4 + 2];
    float py2 = props[g * 4 + 3];
    float w  = px2 - px1;
    float h  = py2 - py1;
    float cx = px1 + 0.5f * w;
    float cy = py1 + 0.5f * h;

    const float fs = 1024.0f;

    float4 bx[2], nbx[2];
    bool   valid[2];
    #pragma unroll
    for (int c = 1; c <= 2; c++) {
        float r0 = breg[g * 12 + 4 * c + 0];
        float r1 = breg[g * 12 + 4 * c + 1];
        float r2 = breg[g * 12 + 4 * c + 2];
        float r3 = breg[g * 12 + 4 * c + 3];
        float dx = r0 / 10.0f;
        float dy = r1 / 10.0f;
        float dw = fminf(r2 / 5.0f, BBOX_CLIP_F);
        float dh = fminf(r3 / 5.0f, BBOX_CLIP_F);
        float pcx = dx * w + cx;
        float pcy = dy * h + cy;
        float pw = expf(dw) * w;
        float ph = expf(dh) * h;
        float x1 = pcx - 0.5f * pw;
        float y1 = pcy - 0.5f * ph;
        float x2 = pcx + 0.5f * pw;
        float y2 = pcy + 0.5f * ph;
        x1 = fminf(fmaxf(x1, 0.0f), fs);
        y1 = fminf(fmaxf(y1, 0.0f), fs);
        x2 = fminf(fmaxf(x2, 0.0f), fs);
        y2 = fminf(fmaxf(y2, 0.0f), fs);

        float s = sc[c - 1];
        valid[c - 1] = (s > 0.3f) && ((x2 - x1) >= 0.01f) && ((y2 - y1) >= 0.01f);
        float off = (float)c * (fs + 1.0f);   // 1025 / 2050 (exact)
        bx[c - 1]  = make_float4(x1, y1, x2, y2);
        nbx[c - 1] = make_float4(x1 + off, y1 + off, x2 + off, y2 + off);
    }

    unsigned m1 = __ballot_sync(0xffffffffu, valid[0]);
    unsigned m2 = __ballot_sync(0xffffffffu, valid[1]);
    int basepos = 0;
    if (lane == 0) basepos = atomicAdd(&g_cnt[b], __popc(m1) + __popc(m2));
    basepos = __shfl_sync(0xffffffffu, basepos, 0);
    unsigned lt = (1u << lane) - 1u;

    int obase = b * M_ENT;
    if (valid[0]) {
        int pos = basepos + __popc(m1 & lt);
        unsigned m = 2u * n + 0u;
        g_cnbox[obase + pos] = nbx[0];
        g_ckey [obase + pos] = pack_key(sc[0], m);
        g_box  [obase + m]   = bx[0];
    }
    if (valid[1]) {
        int pos = basepos + __popc(m1) + __popc(m2 & lt);
        unsigned m = 2u * n + 1u;
        g_cnbox[obase + pos] = nbx[1];
        g_ckey [obase + pos] = pack_key(sc[1], m);
        g_box  [obase + m]   = bx[1];
    }
}

// ---------------------------------------------------------------------------
// cluster helpers
// ---------------------------------------------------------------------------
__device__ __forceinline__ uint32_t smem_u32(const void* p)
{
    uint32_t a;
    asm("{ .reg .u64 t; cvta.to.shared.u64 t, %1; cvt.u32.u64 %0, t; }"
        : "=r"(a) : "l"(p));
    return a;
}

__device__ __forceinline__ void remote_st64(uint32_t laddr, uint32_t rk, u64 v)
{
    uint32_t r;
    asm volatile("mapa.shared::cluster.u32 %0, %1, %2;" : "=r"(r) : "r"(laddr), "r"(rk));
    asm volatile("st.shared::cluster.b64 [%0], %1;" :: "r"(r), "l"(v) : "memory");
}

__device__ __forceinline__ void remote_st128(uint32_t laddr, uint32_t rk, u64 a, u64 b)
{
    uint32_t r;
    asm volatile("mapa.shared::cluster.u32 %0, %1, %2;" : "=r"(r) : "r"(laddr), "r"(rk));
    asm volatile("st.shared::cluster.b64 [%0], %1;"   :: "r"(r), "l"(a) : "memory");
    asm volatile("st.shared::cluster.b64 [%0+8], %1;" :: "r"(r), "l"(b) : "memory");
}

// ---------------------------------------------------------------------------
// NMS: batched greedy selection. Each round: top-8/CTA exchange -> exact
// multi-accept walk over merged 64 -> batched suppression. ~40 selections
// per cluster barrier instead of 1.
// ---------------------------------------------------------------------------
__global__ void __launch_bounds__(T, 1) __cluster_dims__(CLU, 1, 1)
nms_kernel(float* __restrict__ out)
{
    __shared__ u64      xKey[2][CLU][CAND];     // [parity][src rank][cand]
    __shared__ float4   xBox[2][CLU][CAND];
    __shared__ u64      warpRed[T / 32];
    __shared__ unsigned ownT[CAND];             // owner thread of own cand q
    __shared__ int      ownE[CAND];             // owner slot
    __shared__ unsigned rankPos[MC];            // merged idx -> sorted pos
    __shared__ unsigned sortedIdx[MC];          // sorted pos -> merged idx
    __shared__ u64      conf[MC];               // conflict mask (sorted space)
    __shared__ unsigned recIdx[NMS_ITERS];
    __shared__ float    recScore[NMS_ITERS];
    __shared__ int      slots[NMS_ITERS];

    const int t = threadIdx.x;
    const int wrp = t >> 5;
    uint32_t rank;
    asm("mov.u32 %0, %%cluster_ctarank;" : "=r"(rank));
    const int b = blockIdx.x >> 3;
    const int base = b * M_ENT;

    const int cnt = g_cnt[b];

    // owned entries
    u64    key[TSLOTS];
    float4 nb [RSLOTS];
    float  area[RSLOTS];
    #pragma unroll
    for (int e = 0; e < RSLOTS; e++) {
        int c = e * STRIDE + (int)rank * T + t;
        if (c < cnt) {
            key[e]  = g_ckey [base + c];
            nb[e]   = g_cnbox[base + c];
            area[e] = (nb[e].z - nb[e].x) * (nb[e].w - nb[e].y);
        } else {
            key[e]  = 0ull;
            nb[e]   = make_float4(0.f, 0.f, 0.f, 0.f);
            area[e] = 0.f;
        }
    }
    const bool overflow = cnt > RSLOTS * STRIDE;    // uniform; false for this data
    #pragma unroll
    for (int e = RSLOTS; e < TSLOTS; e++) {
        int c = e * STRIDE + (int)rank * T + t;
        key[e] = (overflow && c < cnt) ? g_ckey[base + c] : 0ull;
    }

    int selCount = 0;

    for (int round = 0; round < NMS_ITERS; ++round) {
        const int par = round & 1;

        // ---- 1. extract own top-CAND live candidates (8 block argmaxes) ----
        u64 lmax = 0ull; int wslot = -1;
        #pragma unroll
        for (int e = 0; e < RSLOTS; e++)
            if (key[e] > lmax) { lmax = key[e]; wslot = e; }
        if (overflow) {
            #pragma unroll
            for (int e = RSLOTS; e < TSLOTS; e++)
                if (key[e] > lmax) { lmax = key[e]; wslot = e; }
        }

        for (int p = 0; p < CAND; ++p) {
            unsigned hi = (unsigned)(lmax >> 32);
            unsigned lo = (unsigned)lmax;
            unsigned mhi = __reduce_max_sync(0xffffffffu, hi);
            unsigned mlo = __reduce_max_sync(0xffffffffu, (hi == mhi) ? lo : 0u);
            if ((t & 31) == 0) warpRed[wrp] = ((u64)mhi << 32) | mlo;
            __syncthreads();
            u64 bk = warpRed[0];
            #pragma unroll
            for (int wi = 1; wi < T / 32; wi++) {
                u64 k2 = warpRed[wi];
                bk = (k2 > bk) ? k2 : bk;
            }
            if (bk != 0ull) {
                if (lmax == bk) {          // unique winner thread
                    xKey[par][rank][p] = bk;
                    float4 wb;
                    if (wslot < RSLOTS) wb = nb[wslot];
                    else wb = g_cnbox[base + wslot * STRIDE + (int)rank * T + t];
                    xBox[par][rank][p] = wb;
                    ownT[p] = (unsigned)t;
                    ownE[p] = wslot;
                    key[wslot] = 0ull;
                    // recompute local max
                    lmax = 0ull; wslot = -1;
                    #pragma unroll
                    for (int e = 0; e < RSLOTS; e++)
                        if (key[e] > lmax) { lmax = key[e]; wslot = e; }
                    if (overflow) {
                        #pragma unroll
                        for (int e = RSLOTS; e < TSLOTS; e++)
                            if (key[e] > lmax) { lmax = key[e]; wslot = e; }
                    }
                }
            } else if (t == 0) {
                xKey[par][rank][p] = 0ull;
                xBox[par][rank][p] = make_float4(0.f, 0.f, 0.f, 0.f);
                ownT[p] = 0xFFFFFFFFu;
                ownE[p] = -1;
            }
            __syncthreads();
        }

        // ---- 2. fan-out own candidates to all ranks (64 threads) ----------
        if (t < MC) {
            uint32_t rk = (uint32_t)(t >> 3);
            int q = t & (CAND - 1);
            u64 k  = xKey[par][rank][q];
            float4 bb = xBox[par][rank][q];
            u64 v0 = ((u64)__float_as_uint(bb.y) << 32) | (u64)__float_as_uint(bb.x);
            u64 v1 = ((u64)__float_as_uint(bb.w) << 32) | (u64)__float_as_uint(bb.z);
            remote_st64 (smem_u32(&xKey[par][rank][q]), rk, k);
            remote_st128(smem_u32(&xBox[par][rank][q]), rk, v0, v1);
        }

        // ---- 3. one cluster barrier per round ----------------------------
        asm volatile("barrier.cluster.arrive.aligned;" ::: "memory");
        asm volatile("barrier.cluster.wait.aligned;"   ::: "memory");

        // ---- 4. sort merged 64 by key desc (rank-by-counting) ------------
        if (t < MC) {
            u64 km = xKey[par][t >> 3][t & (CAND - 1)];
            unsigned pos = 0;
            #pragma unroll
            for (int m2 = 0; m2 < MC; m2++) {
                u64 k2 = xKey[par][m2 >> 3][m2 & (CAND - 1)];
                pos += (k2 > km) || (k2 == km && m2 < t);
            }
            rankPos[t] = pos;
            sortedIdx[pos] = (unsigned)t;
            conf[t] = 0ull;
        }
        __syncthreads();

        // pool empty? (uniform)
        {
            unsigned m0 = sortedIdx[0];
            if (xKey[par][m0 >> 3][m0 & (CAND - 1)] == 0ull) break;
        }

        // Kmin = max over ranks of their 8th candidate key
        u64 Kmin = 0ull;
        #pragma unroll
        for (int r = 0; r < CLU; r++) {
            u64 k8 = xKey[par][r][CAND - 1];
            if (k8 > Kmin) Kmin = k8;
        }

        // ---- 5. conflict matrix in sorted space (j = t/4, i-range by t&3) -
        {
            int j = t >> 2;
            int q4 = t & 3;
            if (j < MC) {
                unsigned mj = sortedIdx[j];
                float4 bj = xBox[par][mj >> 3][mj & (CAND - 1)];
                float aj = (bj.z - bj.x) * (bj.w - bj.y);
                u64 m = 0ull;
                int i0 = q4 * 16;
                int i1 = i0 + 16; if (i1 > j) i1 = j;
                for (int i = i0; i < i1; i++) {
                    unsigned mi = sortedIdx[i];
                    float4 bi = xBox[par][mi >> 3][mi & (CAND - 1)];
                    float ai = (bi.z - bi.x) * (bi.w - bi.y);
                    float ltx = fmaxf(bi.x, bj.x);
                    float lty = fmaxf(bi.y, bj.y);
                    float rbx = fminf(bi.z, bj.z);
                    float rby = fminf(bi.w, bj.w);
                    float iw = fmaxf(rbx - ltx, 0.0f);
                    float ih = fmaxf(rby - lty, 0.0f);
                    float inter = iw * ih;
                    float iou = inter / (ai + aj - inter);   // winner area first
                    if (iou > 0.3f) m |= 1ull << i;
                }
                if (m) atomicOr(&conf[j], m);
            }
        }
        __syncthreads();

        // ---- 6. resolve walk (redundant on all threads; uniform) ----------
        u64 acc = 0ull;
        int P_eff = MC;
        {
            int c0 = selCount;
            for (int j = 0; j < MC; j++) {
                unsigned mj = sortedIdx[j];
                u64 kj = xKey[par][mj >> 3][mj & (CAND - 1)];
                if (kj == 0ull || kj < Kmin) { P_eff = j; break; }
                if (c0 == NMS_ITERS)         { P_eff = j; break; }
                if ((conf[j] & acc) == 0ull) {
                    acc |= 1ull << j;
                    if (rank == 0 && t == 0) {
                        recIdx[c0]   = 0xFFFFFFFFu - (unsigned)kj;
                        recScore[c0] = key_score(kj);
                    }
                    c0++;
                }
            }
            selCount = c0;
        }

        // ---- 7. restore own unprocessed candidates ------------------------
        #pragma unroll
        for (int q = 0; q < CAND; q++) {
            if (ownT[q] == (unsigned)t &&
                rankPos[(int)rank * CAND + q] >= (unsigned)P_eff)
                key[ownE[q]] = xKey[par][rank][q];
        }

        // ---- 8. batched suppression vs all accepted winners ---------------
        for (int j = 0; j < P_eff; j++) {
            if (!((acc >> j) & 1ull)) continue;
            unsigned mj = sortedIdx[j];
            float4 wb4 = xBox[par][mj >> 3][mj & (CAND - 1)];
            float a1 = (wb4.z - wb4.x) * (wb4.w - wb4.y);
            #pragma unroll
            for (int e = 0; e < RSLOTS; e++) {
                if (key[e] != 0ull) {
                    float ltx = fmaxf(wb4.x, nb[e].x);
                    float lty = fmaxf(wb4.y, nb[e].y);
                    float rbx = fminf(wb4.z, nb[e].z);
                    float rby = fminf(wb4.w, nb[e].w);
                    float iw = fmaxf(rbx - ltx, 0.0f);
                    float ih = fmaxf(rby - lty, 0.0f);
                    float inter = iw * ih;
                    float iou = inter / (a1 + area[e] - inter);
                    if (iou > 0.3f) key[e] = 0ull;
                }
            }
            if (overflow) {
                #pragma unroll
                for (int e = RSLOTS; e < TSLOTS; e++) {
                    if (key[e] != 0ull) {
                        float4 c4 = g_cnbox[base + e * STRIDE + (int)rank * T + t];
                        float a2 = (c4.z - c4.x) * (c4.w - c4.y);
                        float ltx = fmaxf(wb4.x, c4.x);
                        float lty = fmaxf(wb4.y, c4.y);
                        float rbx = fminf(wb4.z, c4.z);
                        float rby = fminf(wb4.w, c4.w);
                        float iw = fmaxf(rbx - ltx, 0.0f);
                        float ih = fmaxf(rby - lty, 0.0f);
                        float inter = iw * ih;
                        float iou = inter / (a1 + a2 - inter);
                        if (iou > 0.3f) key[e] = 0ull;
                    }
                }
            }
        }

        if (selCount >= NMS_ITERS) break;
    }

    // ------------------- epilogue (rank-0 CTA of each image) ---------------
    __syncthreads();
    if (rank != 0) return;

    const int nRec = selCount;
    float* oBoxes  = out;                         // [8][320][4]
    float* oScores = out + BIMG * DET * 4;        // [8][320]
    float* oLabels = out + BIMG * DET * 5;        // [8][320]

    for (int q = t; q < DET * 4; q += T) oBoxes[b * DET * 4 + q] = 0.0f;
    for (int q = t; q < DET;     q += T) { oScores[b * DET + q] = 0.0f; oLabels[b * DET + q] = 0.0f; }

    if (t == 0) {
        int c0 = 0;
        for (int r = 0; r < nRec; r++)
            if (recScore[r] > HALF_NEG && (recIdx[r] & 1u)) c0++;
        int p0 = 0, p1 = 0;
        for (int r = 0; r < nRec; r++) {
            bool ok = recScore[r] > HALF_NEG;
            int slot = -1;
            if (ok) slot = (recIdx[r] & 1u) ? (p0++) : (c0 + p1++);
            slots[r] = slot;
        }
    }
    __syncthreads();

    for (int q = t; q < nRec; q += T) {
        int slot = slots[q];
        if (slot >= 0 && slot < DET) {
            unsigned i = recIdx[q];
            float4 bx = g_box[base + i];
            float* dst = oBoxes + (b * DET + slot) * 4;
            dst[0] = bx.x; dst[1] = bx.y; dst[2] = bx.z; dst[3] = bx.w;
            oScores[b * DET + slot] = recScore[q];
            oLabels[b * DET + slot] = (float)((i & 1u) + 1u);
        }
    }

    if (t == 0) g_cnt[b] = 0;   // self-clean for next graph replay
}

// ---------------------------------------------------------------------------
extern "C" void kernel_launch(void* const* d_in, const int* in_sizes, int n_in,
                              void* d_out, int out_size)
{
    (void)in_sizes; (void)n_in; (void)out_size;
    const float* logits = (const float*)d_in[0];
    const float* breg   = (const float*)d_in[1];
    const float* props  = (const float*)d_in[2];
    float* out = (float*)d_out;

    prep_kernel<<<BN / 256, 256>>>(logits, breg, props);
    nms_kernel<<<BIMG * CLU, T>>>(out);
}